// round 1
// baseline (speedup 1.0000x reference)
#include <cuda_runtime.h>
#include <math.h>

// NTXentLoss: N=4096, D=512, 2N=8192 rows.
// z = concat(z1,z2); zn = z/max(||z||,eps); sim = zn zn^T / T; diag -> -inf;
// loss_i = -sim[i, partner(i)] + logsumexp_j(sim[i,j]); out = mean(loss).
//
// Strategy (round 1 baseline):
//  - normalize kernel -> g_zn (fp32, L2-resident 16.8MB), also zeros g_rowsum
//  - fused tiled "GEMM" over UPPER-TRIANGULAR 128x128 tile pairs only
//    (sim is exactly symmetric), epilogue applies exp(sim - 1/T) and
//    scatters into row sums AND col sums (col==row sums by symmetry).
//  - positives written directly when (i, i+N) element is computed (mirrored).
//  - final reduction kernel -> scalar mean.

#define TWO_N   8192
#define NHALF   4096
#define D       512
#define INV_T   14.285714285714286f         // 1/0.07
#define LOG2E   1.4426950408889634f
#define EXP_SCALE (INV_T * LOG2E)           // arg = dot*EXP_SCALE - EXP_SCALE

__device__ static float g_zn[TWO_N * D];    // normalized rows
__device__ static float g_rowsum[TWO_N];    // sum_j exp(sim_ij - 1/T), diag excluded
__device__ static float g_pos[TWO_N];       // sim[i, partner(i)]

// ---------------------------------------------------------------------------
// Kernel 1: row normalize (one block of 128 threads per row) + zero rowsum
// ---------------------------------------------------------------------------
__global__ void k_normalize(const float* __restrict__ z1,
                            const float* __restrict__ z2) {
    const int row = blockIdx.x;
    const int tid = threadIdx.x;            // 128 threads, 4 floats each
    const float* src = (row < NHALF) ? (z1 + (size_t)row * D)
                                     : (z2 + (size_t)(row - NHALF) * D);
    float4 v = ((const float4*)src)[tid];
    float ss = v.x * v.x + v.y * v.y + v.z * v.z + v.w * v.w;

    // warp reduce
    #pragma unroll
    for (int off = 16; off > 0; off >>= 1)
        ss += __shfl_xor_sync(0xffffffffu, ss, off);

    __shared__ float s_part[4];
    __shared__ float s_inv;
    const int wid = tid >> 5;
    if ((tid & 31) == 0) s_part[wid] = ss;
    __syncthreads();
    if (tid == 0) {
        float total = s_part[0] + s_part[1] + s_part[2] + s_part[3];
        float nrm = sqrtf(total);
        s_inv = 1.0f / fmaxf(nrm, 1e-8f);
        g_rowsum[row] = 0.0f;
    }
    __syncthreads();
    const float inv = s_inv;
    float4 o;
    o.x = v.x * inv; o.y = v.y * inv; o.z = v.z * inv; o.w = v.w * inv;
    ((float4*)(g_zn + (size_t)row * D))[tid] = o;
}

// ---------------------------------------------------------------------------
// Kernel 2: fused sim+exp+reduce over upper-triangular 128x128 tiles.
// 256 threads, 16x16 thread grid, 8x8 microtile per thread, BK=16.
// ---------------------------------------------------------------------------
#define BM 128
#define BN 128
#define BK 16
#define SPAD 132   // padded smem row (floats); keeps float4 alignment (132*4=528=16*33)

__global__ __launch_bounds__(256, 2) void k_sim() {
    const int bx = blockIdx.x;   // col tile
    const int by = blockIdx.y;   // row tile
    if (bx < by) return;         // symmetric: upper triangle only (uniform exit)

    __shared__ float As[BK][SPAD];
    __shared__ float Bs[BK][SPAD];
    __shared__ float s_colsum[BN];

    const int tid = threadIdx.x;
    const int tx = tid & 15;     // col group
    const int ty = tid >> 4;     // row group

    const int rowbase = by * BM;
    const int colbase = bx * BN;
    const float* __restrict__ Ag = g_zn + (size_t)rowbase * D;
    const float* __restrict__ Bg = g_zn + (size_t)colbase * D;

    float acc[8][8];
    #pragma unroll
    for (int i = 0; i < 8; i++)
        #pragma unroll
        for (int j = 0; j < 8; j++) acc[i][j] = 0.0f;

    for (int k0 = 0; k0 < D; k0 += BK) {
        // load 128x16 A and B tiles (transposed into smem), float4 global reads
        #pragma unroll
        for (int l = 0; l < 2; l++) {
            int idx = tid + l * 256;          // float4 index within tile
            int r   = idx >> 2;               // 0..127
            int c4  = (idx & 3) * 4;          // 0,4,8,12
            float4 a = *(const float4*)(Ag + (size_t)r * D + k0 + c4);
            As[c4 + 0][r] = a.x; As[c4 + 1][r] = a.y;
            As[c4 + 2][r] = a.z; As[c4 + 3][r] = a.w;
            float4 b = *(const float4*)(Bg + (size_t)r * D + k0 + c4);
            Bs[c4 + 0][r] = b.x; Bs[c4 + 1][r] = b.y;
            Bs[c4 + 2][r] = b.z; Bs[c4 + 3][r] = b.w;
        }
        __syncthreads();

        #pragma unroll
        for (int kk = 0; kk < BK; kk++) {
            float a[8], b[8];
            *(float4*)(a)     = *(const float4*)&As[kk][ty * 8];
            *(float4*)(a + 4) = *(const float4*)&As[kk][ty * 8 + 4];
            *(float4*)(b)     = *(const float4*)&Bs[kk][tx * 8];
            *(float4*)(b + 4) = *(const float4*)&Bs[kk][tx * 8 + 4];
            #pragma unroll
            for (int i = 0; i < 8; i++)
                #pragma unroll
                for (int j = 0; j < 8; j++)
                    acc[i][j] = fmaf(a[i], b[j], acc[i][j]);
        }
        __syncthreads();
    }

    // ---- epilogue: exp(sim - 1/T), diag mask, positives, row+col sums ----
    const bool diagblk = (bx == by);
    float rowpart[8], colpart[8];
    #pragma unroll
    for (int i = 0; i < 8; i++) { rowpart[i] = 0.0f; colpart[i] = 0.0f; }

    #pragma unroll
    for (int i = 0; i < 8; i++) {
        const int gi = rowbase + ty * 8 + i;
        #pragma unroll
        for (int j = 0; j < 8; j++) {
            const int gj = colbase + tx * 8 + j;
            const float dot = acc[i][j];
            float e = exp2f(fmaf(dot, EXP_SCALE, -EXP_SCALE)); // exp(sim - 1/T)
            if (gj == gi) e = 0.0f;                             // diagonal mask
            rowpart[i] += e;
            colpart[j] += e;
            if (gj == gi + NHALF) {                             // positive pair
                const float s = dot * INV_T;
                g_pos[gi] = s;            // upper positive
                g_pos[gj] = s;            // lower positive (exact symmetry)
            }
        }
    }

    // row reduce across tx (tx = low 4 bits of lane id)
    #pragma unroll
    for (int i = 0; i < 8; i++) {
        #pragma unroll
        for (int off = 1; off < 16; off <<= 1)
            rowpart[i] += __shfl_xor_sync(0xffffffffu, rowpart[i], off);
    }
    if (tx == 0) {
        #pragma unroll
        for (int i = 0; i < 8; i++)
            atomicAdd(&g_rowsum[rowbase + ty * 8 + i], rowpart[i]);
    }

    // col reduce (only off-diagonal blocks contribute the mirrored half)
    if (!diagblk) {
        if (tid < BN) s_colsum[tid] = 0.0f;
        __syncthreads();
        #pragma unroll
        for (int j = 0; j < 8; j++)
            atomicAdd(&s_colsum[tx * 8 + j], colpart[j]);
        __syncthreads();
        if (tid < BN)
            atomicAdd(&g_rowsum[colbase + tid], s_colsum[tid]);
    }
}

// ---------------------------------------------------------------------------
// Kernel 3: loss_i = -pos_i + 1/T + log(rowsum_i); output mean
// ---------------------------------------------------------------------------
__global__ void k_final(float* __restrict__ out) {
    const int tid = threadIdx.x;   // 256
    float sum = 0.0f;
    for (int r = tid; r < TWO_N; r += 256)
        sum += -g_pos[r] + INV_T + logf(g_rowsum[r]);

    __shared__ float red[256];
    red[tid] = sum;
    __syncthreads();
    #pragma unroll
    for (int s = 128; s > 0; s >>= 1) {
        if (tid < s) red[tid] += red[tid + s];
        __syncthreads();
    }
    if (tid == 0) out[0] = red[0] / (float)TWO_N;
}

extern "C" void kernel_launch(void* const* d_in, const int* in_sizes, int n_in,
                              void* d_out, int out_size) {
    const float* z1 = (const float*)d_in[0];
    const float* z2 = (const float*)d_in[1];
    float* out = (float*)d_out;

    k_normalize<<<TWO_N, 128>>>(z1, z2);
    dim3 grid(TWO_N / BN, TWO_N / BM);
    k_sim<<<grid, 256>>>();
    k_final<<<1, 256>>>(out);
}

// round 3
// speedup vs baseline: 6.2227x; 6.2227x over previous
#include <cuda_runtime.h>
#include <cuda_bf16.h>
#include <cstdint>
#include <math.h>

// NTXentLoss: bf16 mma.sync (HMMA) GEMM over upper-triangular 128x128 tiles,
// register accumulators, fused exp/row+col reduction. N=4096, D=512, 2N=8192.
// (tcgen05 unavailable: harness PTX stage targets compute_103 non-'a'.)

#define TWO_N   8192
#define NHALF   4096
#define DDIM    512
#define INV_T   14.285714285714286f
#define LOG2E   1.4426950408889634f
#define EXP_SCALE (INV_T * LOG2E)

#define BM 128
#define BN 128
#define BKC 64                       // K per chunk: 64 bf16 = 128B rows
#define NCHUNK (DDIM / BKC)          // 8
#define TILE_B (BM * 128)            // 16384 bytes per operand chunk
// dynamic smem: A0,A1,B0,B1
#define SMEM_BYTES (4 * TILE_B)

__device__ static __nv_bfloat16 g_zn[TWO_N * DDIM];
__device__ static float g_rowsum[TWO_N];
__device__ static float g_pos[TWO_N];

__device__ __forceinline__ uint32_t smem_u32(const void* p) {
    uint32_t a;
    asm("{ .reg .u64 t; cvta.to.shared.u64 t, %1; cvt.u32.u64 %0, t; }"
        : "=r"(a) : "l"(p));
    return a;
}
#define CP16(dst, src) \
    asm volatile("cp.async.cg.shared.global [%0], [%1], 16;" :: "r"(dst), "l"(src))
#define CPCOMMIT() asm volatile("cp.async.commit_group;" ::: "memory")

#define LDSM4(r0, r1, r2, r3, addr)                                         \
    asm volatile("ldmatrix.sync.aligned.m8n8.x4.shared.b16 {%0,%1,%2,%3}, [%4];" \
        : "=r"(r0), "=r"(r1), "=r"(r2), "=r"(r3) : "r"(addr))

#define MMA16816(c, a, b0, b1)                                              \
    asm volatile("mma.sync.aligned.m16n8k16.row.col.f32.bf16.bf16.f32 "     \
        "{%0,%1,%2,%3}, {%4,%5,%6,%7}, {%8,%9}, {%0,%1,%2,%3};"             \
        : "+f"((c)[0]), "+f"((c)[1]), "+f"((c)[2]), "+f"((c)[3])            \
        : "r"((a)[0]), "r"((a)[1]), "r"((a)[2]), "r"((a)[3]),               \
          "r"(b0), "r"(b1))

// ---------------------------------------------------------------------------
// Kernel 1: normalize rows -> bf16, zero rowsums
// ---------------------------------------------------------------------------
__global__ void k_normalize(const float* __restrict__ z1,
                            const float* __restrict__ z2) {
    const int row = blockIdx.x;
    const int tid = threadIdx.x;   // 128, 4 floats each
    const float* src = (row < NHALF) ? (z1 + (size_t)row * DDIM)
                                     : (z2 + (size_t)(row - NHALF) * DDIM);
    float4 v = ((const float4*)src)[tid];
    float ss = v.x * v.x + v.y * v.y + v.z * v.z + v.w * v.w;
    #pragma unroll
    for (int off = 16; off > 0; off >>= 1)
        ss += __shfl_xor_sync(0xffffffffu, ss, off);

    __shared__ float s_part[4];
    __shared__ float s_inv;
    if ((tid & 31) == 0) s_part[tid >> 5] = ss;
    __syncthreads();
    if (tid == 0) {
        float total = s_part[0] + s_part[1] + s_part[2] + s_part[3];
        s_inv = 1.0f / fmaxf(sqrtf(total), 1e-8f);
        g_rowsum[row] = 0.0f;
    }
    __syncthreads();
    const float inv = s_inv;
    __nv_bfloat162 p0, p1;
    p0.x = __float2bfloat16(v.x * inv); p0.y = __float2bfloat16(v.y * inv);
    p1.x = __float2bfloat16(v.z * inv); p1.y = __float2bfloat16(v.w * inv);
    __nv_bfloat162* dst = (__nv_bfloat162*)(g_zn + (size_t)row * DDIM);
    dst[tid * 2]     = p0;
    dst[tid * 2 + 1] = p1;
}

// ---------------------------------------------------------------------------
// Kernel 2: 128x128 tiles, 8 warps (wm 0..1 x wn 0..3), warp tile 64x32.
// Smem chunk layout: 128 rows x 8 segs(16B), seg swizzled by (row&7).
// ---------------------------------------------------------------------------
__device__ __forceinline__ void load_chunk(uint32_t base, const char* gsrc,
                                           int c, int tid) {
    #pragma unroll
    for (int i = 0; i < 4; i++) {
        int idx = tid + i * 256;        // 0..1023
        int r = idx >> 3, s = idx & 7;
        uint32_t off = (uint32_t)(r * 128 + ((s ^ (r & 7)) * 16));
        CP16(base + off, gsrc + (size_t)r * 1024 + (size_t)c * 128 + s * 16);
    }
}

__global__ void __launch_bounds__(256, 2) k_sim() {
    const int bx = blockIdx.x;          // col tile
    const int by = blockIdx.y;          // row tile
    if (bx < by) return;                // upper triangle only

    extern __shared__ char smraw[];
    const uint32_t sA[2] = { smem_u32(smraw), smem_u32(smraw) + TILE_B };
    const uint32_t sB[2] = { sA[1] + TILE_B, sA[1] + 2 * TILE_B };

    __shared__ float rowsum_s[BM];
    __shared__ float colsum_s[BN];

    const int tid  = threadIdx.x;
    const int wid  = tid >> 5;
    const int lane = tid & 31;
    const int wm = wid & 1;             // 2 warps in M
    const int wn = wid >> 1;            // 4 warps in N

    if (tid < BM) rowsum_s[tid] = 0.0f;
    if (tid < BN) colsum_s[tid] = 0.0f;

    const int rowbase = by * BM;
    const int colbase = bx * BN;
    const char* gA = (const char*)(g_zn + (size_t)rowbase * DDIM);
    const char* gB = (const char*)(g_zn + (size_t)colbase * DDIM);

    float acc[4][4][4];
    #pragma unroll
    for (int i = 0; i < 4; i++)
        #pragma unroll
        for (int j = 0; j < 4; j++)
            #pragma unroll
            for (int v = 0; v < 4; v++) acc[i][j][v] = 0.0f;

    // ldmatrix address pieces (row = base + (lane&15), seg = 2*kk + (lane>>4))
    const int lrow = lane & 15;
    const int lseg = lane >> 4;

    load_chunk(sA[0], gA, 0, tid);
    load_chunk(sB[0], gB, 0, tid);
    CPCOMMIT();

    #pragma unroll 1
    for (int c = 0; c < NCHUNK; c++) {
        const int buf = c & 1;
        if (c < NCHUNK - 1) {
            load_chunk(sA[buf ^ 1], gA, c + 1, tid);
            load_chunk(sB[buf ^ 1], gB, c + 1, tid);
            CPCOMMIT();
            asm volatile("cp.async.wait_group 1;" ::: "memory");
        } else {
            asm volatile("cp.async.wait_group 0;" ::: "memory");
        }
        __syncthreads();

        #pragma unroll
        for (int kk = 0; kk < 4; kk++) {            // 4 x k16 per chunk
            const int seg = 2 * kk + lseg;
            uint32_t a[4][4], b[2][4];
            #pragma unroll
            for (int mi = 0; mi < 4; mi++) {
                int r = wm * 64 + mi * 16 + lrow;
                uint32_t addr = sA[buf] + (uint32_t)(r * 128 + ((seg ^ (r & 7)) * 16));
                LDSM4(a[mi][0], a[mi][1], a[mi][2], a[mi][3], addr);
            }
            #pragma unroll
            for (int bt = 0; bt < 2; bt++) {
                int r = wn * 32 + bt * 16 + lrow;
                uint32_t addr = sB[buf] + (uint32_t)(r * 128 + ((seg ^ (r & 7)) * 16));
                LDSM4(b[bt][0], b[bt][1], b[bt][2], b[bt][3], addr);
            }
            #pragma unroll
            for (int mi = 0; mi < 4; mi++)
                #pragma unroll
                for (int bt = 0; bt < 2; bt++) {
                    MMA16816(acc[mi][bt * 2 + 0], a[mi], b[bt][0], b[bt][2]);
                    MMA16816(acc[mi][bt * 2 + 1], a[mi], b[bt][1], b[bt][3]);
                }
        }
        __syncthreads();
    }

    // ---- epilogue ----
    const int qr = lane >> 2;           // 0..7 row-in-tile
    const int qc = (lane & 3) * 2;      // col pair base
    float colp[4][2];
    #pragma unroll
    for (int nt = 0; nt < 4; nt++) { colp[nt][0] = 0.0f; colp[nt][1] = 0.0f; }

    #pragma unroll
    for (int mi = 0; mi < 4; mi++) {
        const int gi0 = rowbase + wm * 64 + mi * 16 + qr;
        const int gi1 = gi0 + 8;
        float rs0 = 0.0f, rs1 = 0.0f;
        #pragma unroll
        for (int nt = 0; nt < 4; nt++) {
            const int gj0 = colbase + wn * 32 + nt * 8 + qc;
            const int gj1 = gj0 + 1;
            const float d00 = acc[mi][nt][0], d01 = acc[mi][nt][1];
            const float d10 = acc[mi][nt][2], d11 = acc[mi][nt][3];

            float e00 = exp2f(fmaf(d00, EXP_SCALE, -EXP_SCALE));
            float e01 = exp2f(fmaf(d01, EXP_SCALE, -EXP_SCALE));
            float e10 = exp2f(fmaf(d10, EXP_SCALE, -EXP_SCALE));
            float e11 = exp2f(fmaf(d11, EXP_SCALE, -EXP_SCALE));
            if (gj0 <= gi0) e00 = 0.0f;
            if (gj1 <= gi0) e01 = 0.0f;
            if (gj0 <= gi1) e10 = 0.0f;
            if (gj1 <= gi1) e11 = 0.0f;

            if (gj0 == gi0 + NHALF) { float s = d00 * INV_T; g_pos[gi0] = s; g_pos[gj0] = s; }
            if (gj1 == gi0 + NHALF) { float s = d01 * INV_T; g_pos[gi0] = s; g_pos[gj1] = s; }
            if (gj0 == gi1 + NHALF) { float s = d10 * INV_T; g_pos[gi1] = s; g_pos[gj0] = s; }
            if (gj1 == gi1 + NHALF) { float s = d11 * INV_T; g_pos[gi1] = s; g_pos[gj1] = s; }

            rs0 += e00 + e01;
            rs1 += e10 + e11;
            colp[nt][0] += e00 + e10;
            colp[nt][1] += e01 + e11;
        }
        // row reduce across the 4 lanes of the quad (cols)
        rs0 += __shfl_xor_sync(0xffffffffu, rs0, 1);
        rs0 += __shfl_xor_sync(0xffffffffu, rs0, 2);
        rs1 += __shfl_xor_sync(0xffffffffu, rs1, 1);
        rs1 += __shfl_xor_sync(0xffffffffu, rs1, 2);
        if ((lane & 3) == 0) {
            atomicAdd(&rowsum_s[wm * 64 + mi * 16 + qr], rs0);
            atomicAdd(&rowsum_s[wm * 64 + mi * 16 + qr + 8], rs1);
        }
    }
    // col reduce across the 8 row-groups
    #pragma unroll
    for (int nt = 0; nt < 4; nt++) {
        #pragma unroll
        for (int j = 0; j < 2; j++) {
            float v = colp[nt][j];
            v += __shfl_xor_sync(0xffffffffu, v, 4);
            v += __shfl_xor_sync(0xffffffffu, v, 8);
            v += __shfl_xor_sync(0xffffffffu, v, 16);
            if (lane < 4 && (lane & 3) == (qc >> 1))  // lane qc/2 owns this col pair
                atomicAdd(&colsum_s[wn * 32 + nt * 8 + qc + j], v);
        }
    }
    __syncthreads();

    if (tid < BM) atomicAdd(&g_rowsum[rowbase + tid], rowsum_s[tid]);
    if (tid < BN) atomicAdd(&g_rowsum[colbase + tid], colsum_s[tid]);
}

// ---------------------------------------------------------------------------
// Kernel 3: loss_i = -pos_i + 1/T + log(rowsum_i); mean
// ---------------------------------------------------------------------------
__global__ void k_final(float* __restrict__ out) {
    const int tid = threadIdx.x;    // 1024
    float sum = 0.0f;
    for (int r = tid; r < TWO_N; r += 1024)
        sum += -g_pos[r] + INV_T + logf(g_rowsum[r]);
    #pragma unroll
    for (int off = 16; off > 0; off >>= 1)
        sum += __shfl_xor_sync(0xffffffffu, sum, off);
    __shared__ float red[32];
    if ((tid & 31) == 0) red[tid >> 5] = sum;
    __syncthreads();
    if (tid < 32) {
        float v = red[tid];
        #pragma unroll
        for (int off = 16; off > 0; off >>= 1)
            v += __shfl_xor_sync(0xffffffffu, v, off);
        if (tid == 0) out[0] = v / (float)TWO_N;
    }
}

extern "C" void kernel_launch(void* const* d_in, const int* in_sizes, int n_in,
                              void* d_out, int out_size) {
    const float* z1 = (const float*)d_in[0];
    const float* z2 = (const float*)d_in[1];
    float* out = (float*)d_out;

    static int attr_set = 0;
    if (!attr_set) {
        cudaFuncSetAttribute(k_sim, cudaFuncAttributeMaxDynamicSharedMemorySize,
                             SMEM_BYTES);
        attr_set = 1;
    }

    k_normalize<<<TWO_N, 128>>>(z1, z2);
    dim3 grid(TWO_N / BN, TWO_N / BM);   // (64, 64), lower half exits
    k_sim<<<grid, 256, SMEM_BYTES>>>();
    k_final<<<1, 1024>>>(out);
}

// round 4
// speedup vs baseline: 6.5533x; 1.0531x over previous
#include <cuda_runtime.h>
#include <cuda_bf16.h>
#include <cstdint>
#include <math.h>

// NTXentLoss: bf16 mma.sync (HMMA) over upper-triangular 128x128 tiles,
// 3-stage cp.async pipeline, fused exp/row+col reduction. 2N=8192, D=512.

#define TWO_N   8192
#define NHALF   4096
#define DDIM    512
#define INV_T   14.285714285714286f
#define LOG2E   1.4426950408889634f
#define EXP_SCALE (INV_T * LOG2E)

#define BM 128
#define BN 128
#define NCHUNK 8                     // K chunks of 64
#define TILE_B (BM * 128)            // 16KB per operand chunk
#define NSTAGE 3
#define SMEM_BYTES (2 * NSTAGE * TILE_B)   // 96KB

#define NTILE 64                     // 8192/128
#define NUPPER 2080                  // 64*65/2

__device__ static __nv_bfloat16 g_zn[TWO_N * DDIM];
__device__ static float g_rowsum[TWO_N];
__device__ static float g_pos[TWO_N];
__device__ static float g_part[32];

__device__ __forceinline__ uint32_t smem_u32(const void* p) {
    uint32_t a;
    asm("{ .reg .u64 t; cvta.to.shared.u64 t, %1; cvt.u32.u64 %0, t; }"
        : "=r"(a) : "l"(p));
    return a;
}
#define CP16(dst, src) \
    asm volatile("cp.async.cg.shared.global [%0], [%1], 16;" :: "r"(dst), "l"(src))
#define CPCOMMIT() asm volatile("cp.async.commit_group;" ::: "memory")

#define LDSM4(r0, r1, r2, r3, addr)                                         \
    asm volatile("ldmatrix.sync.aligned.m8n8.x4.shared.b16 {%0,%1,%2,%3}, [%4];" \
        : "=r"(r0), "=r"(r1), "=r"(r2), "=r"(r3) : "r"(addr))

#define MMA16816(c, a, b0, b1)                                              \
    asm volatile("mma.sync.aligned.m16n8k16.row.col.f32.bf16.bf16.f32 "     \
        "{%0,%1,%2,%3}, {%4,%5,%6,%7}, {%8,%9}, {%0,%1,%2,%3};"             \
        : "+f"((c)[0]), "+f"((c)[1]), "+f"((c)[2]), "+f"((c)[3])            \
        : "r"((a)[0]), "r"((a)[1]), "r"((a)[2]), "r"((a)[3]),               \
          "r"(b0), "r"(b1))

// ---------------------------------------------------------------------------
// Kernel 1: one warp per row: normalize -> bf16, zero rowsum. No block sync.
// ---------------------------------------------------------------------------
__global__ void k_normalize(const float* __restrict__ z1,
                            const float* __restrict__ z2) {
    const int row  = (blockIdx.x * blockDim.x + threadIdx.x) >> 5;
    const int lane = threadIdx.x & 31;
    const float* src = (row < NHALF) ? (z1 + (size_t)row * DDIM)
                                     : (z2 + (size_t)(row - NHALF) * DDIM);
    float4 v[4];
    float ss = 0.0f;
    #pragma unroll
    for (int i = 0; i < 4; i++) {
        v[i] = ((const float4*)src)[lane + 32 * i];
        ss += v[i].x * v[i].x + v[i].y * v[i].y + v[i].z * v[i].z + v[i].w * v[i].w;
    }
    #pragma unroll
    for (int off = 16; off > 0; off >>= 1)
        ss += __shfl_xor_sync(0xffffffffu, ss, off);
    const float inv = 1.0f / fmaxf(sqrtf(ss), 1e-8f);
    if (lane == 0) g_rowsum[row] = 0.0f;

    __nv_bfloat162* dst = (__nv_bfloat162*)(g_zn + (size_t)row * DDIM);
    #pragma unroll
    for (int i = 0; i < 4; i++) {
        __nv_bfloat162 p0, p1;
        p0.x = __float2bfloat16(v[i].x * inv); p0.y = __float2bfloat16(v[i].y * inv);
        p1.x = __float2bfloat16(v[i].z * inv); p1.y = __float2bfloat16(v[i].w * inv);
        dst[(lane + 32 * i) * 2]     = p0;
        dst[(lane + 32 * i) * 2 + 1] = p1;
    }
}

// ---------------------------------------------------------------------------
// Kernel 2: 128x128 tiles, 8 warps (2x4), warp tile 64x32, 3-stage pipeline.
// ---------------------------------------------------------------------------
__device__ __forceinline__ void load_chunk(uint32_t base, const char* gsrc,
                                           int c, int tid) {
    #pragma unroll
    for (int i = 0; i < 4; i++) {
        int idx = tid + i * 256;        // 0..1023
        int r = idx >> 3, s = idx & 7;
        uint32_t off = (uint32_t)(r * 128 + ((s ^ (r & 7)) * 16));
        CP16(base + off, gsrc + (size_t)r * 1024 + (size_t)c * 128 + s * 16);
    }
}

__global__ void __launch_bounds__(256, 2) k_sim() {
    // decode upper-triangular tile index (row-major): by <= bx < 64
    const int t = blockIdx.x;
    int by = (int)(64.5f - sqrtf(64.5f * 64.5f - 2.0f * (float)t));
    while ((by + 1) * NTILE - ((by + 1) * by) / 2 <= t) by++;
    while (by * NTILE - (by * (by - 1)) / 2 > t) by--;
    const int bx = by + (t - (by * NTILE - (by * (by - 1)) / 2));

    extern __shared__ char smraw[];
    uint32_t sA[NSTAGE], sB[NSTAGE];
    #pragma unroll
    for (int i = 0; i < NSTAGE; i++) {
        sA[i] = smem_u32(smraw) + i * TILE_B;
        sB[i] = smem_u32(smraw) + (NSTAGE + i) * TILE_B;
    }

    __shared__ float rowsum_s[BM];
    __shared__ float colsum_s[BN];

    const int tid  = threadIdx.x;
    const int wid  = tid >> 5;
    const int lane = tid & 31;
    const int wm = wid & 1;
    const int wn = wid >> 1;

    if (tid < BM) rowsum_s[tid] = 0.0f;
    if (tid < BN) colsum_s[tid] = 0.0f;

    const int rowbase = by * BM;
    const int colbase = bx * BN;
    const char* gA = (const char*)(g_zn + (size_t)rowbase * DDIM);
    const char* gB = (const char*)(g_zn + (size_t)colbase * DDIM);

    float acc[4][4][4];
    #pragma unroll
    for (int i = 0; i < 4; i++)
        #pragma unroll
        for (int j = 0; j < 4; j++)
            #pragma unroll
            for (int v = 0; v < 4; v++) acc[i][j][v] = 0.0f;

    const int lrow = lane & 15;
    const int lseg = lane >> 4;

    load_chunk(sA[0], gA, 0, tid); load_chunk(sB[0], gB, 0, tid); CPCOMMIT();
    load_chunk(sA[1], gA, 1, tid); load_chunk(sB[1], gB, 1, tid); CPCOMMIT();

    int cur = 0;
    #pragma unroll 1
    for (int c = 0; c < NCHUNK; c++) {
        __syncthreads();                 // chunk c-1 fully consumed by all warps
        if (c + 2 < NCHUNK) {
            int wb = cur + 2 >= NSTAGE ? cur + 2 - NSTAGE : cur + 2;
            load_chunk(sA[wb], gA, c + 2, tid);
            load_chunk(sB[wb], gB, c + 2, tid);
            CPCOMMIT();
            asm volatile("cp.async.wait_group 2;" ::: "memory");
        } else if (c + 1 < NCHUNK) {
            asm volatile("cp.async.wait_group 1;" ::: "memory");
        } else {
            asm volatile("cp.async.wait_group 0;" ::: "memory");
        }
        __syncthreads();

        #pragma unroll
        for (int kk = 0; kk < 4; kk++) {
            const int seg = 2 * kk + lseg;
            uint32_t a[4][4], b[2][4];
            #pragma unroll
            for (int mi = 0; mi < 4; mi++) {
                int r = wm * 64 + mi * 16 + lrow;
                uint32_t addr = sA[cur] + (uint32_t)(r * 128 + ((seg ^ (r & 7)) * 16));
                LDSM4(a[mi][0], a[mi][1], a[mi][2], a[mi][3], addr);
            }
            #pragma unroll
            for (int bt = 0; bt < 2; bt++) {
                int r = wn * 32 + bt * 16 + lrow;
                uint32_t addr = sB[cur] + (uint32_t)(r * 128 + ((seg ^ (r & 7)) * 16));
                LDSM4(b[bt][0], b[bt][1], b[bt][2], b[bt][3], addr);
            }
            #pragma unroll
            for (int mi = 0; mi < 4; mi++)
                #pragma unroll
                for (int bt = 0; bt < 2; bt++) {
                    MMA16816(acc[mi][bt * 2 + 0], a[mi], b[bt][0], b[bt][2]);
                    MMA16816(acc[mi][bt * 2 + 1], a[mi], b[bt][1], b[bt][3]);
                }
        }
        cur = cur + 1 >= NSTAGE ? 0 : cur + 1;
    }

    // ---- epilogue ----
    const int qr = lane >> 2;
    const int qc = (lane & 3) * 2;
    float colp[4][2];
    #pragma unroll
    for (int nt = 0; nt < 4; nt++) { colp[nt][0] = 0.0f; colp[nt][1] = 0.0f; }

    #pragma unroll
    for (int mi = 0; mi < 4; mi++) {
        const int gi0 = rowbase + wm * 64 + mi * 16 + qr;
        const int gi1 = gi0 + 8;
        float rs0 = 0.0f, rs1 = 0.0f;
        #pragma unroll
        for (int nt = 0; nt < 4; nt++) {
            const int gj0 = colbase + wn * 32 + nt * 8 + qc;
            const int gj1 = gj0 + 1;
            const float d00 = acc[mi][nt][0], d01 = acc[mi][nt][1];
            const float d10 = acc[mi][nt][2], d11 = acc[mi][nt][3];

            float e00 = exp2f(fmaf(d00, EXP_SCALE, -EXP_SCALE));
            float e01 = exp2f(fmaf(d01, EXP_SCALE, -EXP_SCALE));
            float e10 = exp2f(fmaf(d10, EXP_SCALE, -EXP_SCALE));
            float e11 = exp2f(fmaf(d11, EXP_SCALE, -EXP_SCALE));
            if (gj0 <= gi0) e00 = 0.0f;
            if (gj1 <= gi0) e01 = 0.0f;
            if (gj0 <= gi1) e10 = 0.0f;
            if (gj1 <= gi1) e11 = 0.0f;

            if (gj0 == gi0 + NHALF) { float s = d00 * INV_T; g_pos[gi0] = s; g_pos[gj0] = s; }
            if (gj1 == gi0 + NHALF) { float s = d01 * INV_T; g_pos[gi0] = s; g_pos[gj1] = s; }
            if (gj0 == gi1 + NHALF) { float s = d10 * INV_T; g_pos[gi1] = s; g_pos[gj0] = s; }
            if (gj1 == gi1 + NHALF) { float s = d11 * INV_T; g_pos[gi1] = s; g_pos[gj1] = s; }

            rs0 += e00 + e01;
            rs1 += e10 + e11;
            colp[nt][0] += e00 + e10;
            colp[nt][1] += e01 + e11;
        }
        rs0 += __shfl_xor_sync(0xffffffffu, rs0, 1);
        rs0 += __shfl_xor_sync(0xffffffffu, rs0, 2);
        rs1 += __shfl_xor_sync(0xffffffffu, rs1, 1);
        rs1 += __shfl_xor_sync(0xffffffffu, rs1, 2);
        if ((lane & 3) == 0) {
            atomicAdd(&rowsum_s[wm * 64 + mi * 16 + qr], rs0);
            atomicAdd(&rowsum_s[wm * 64 + mi * 16 + qr + 8], rs1);
        }
    }
    #pragma unroll
    for (int nt = 0; nt < 4; nt++) {
        #pragma unroll
        for (int j = 0; j < 2; j++) {
            float v = colp[nt][j];
            v += __shfl_xor_sync(0xffffffffu, v, 4);
            v += __shfl_xor_sync(0xffffffffu, v, 8);
            v += __shfl_xor_sync(0xffffffffu, v, 16);
            if (lane < 4 && (lane & 3) == (qc >> 1))
                atomicAdd(&colsum_s[wn * 32 + nt * 8 + qc + j], v);
        }
    }
    __syncthreads();

    if (tid < BM) atomicAdd(&g_rowsum[rowbase + tid], rowsum_s[tid]);
    if (tid < BN) atomicAdd(&g_rowsum[colbase + tid], colsum_s[tid]);
}

// ---------------------------------------------------------------------------
// Kernel 3a: per-block partial loss sums (32 blocks x 256 rows)
// ---------------------------------------------------------------------------
__global__ void k_final1() {
    const int tid = threadIdx.x;
    const int r = blockIdx.x * 256 + tid;
    float v = -g_pos[r] + INV_T + logf(g_rowsum[r]);
    #pragma unroll
    for (int off = 16; off > 0; off >>= 1)
        v += __shfl_xor_sync(0xffffffffu, v, off);
    __shared__ float red[8];
    if ((tid & 31) == 0) red[tid >> 5] = v;
    __syncthreads();
    if (tid < 8) {
        float s = red[tid];
        #pragma unroll
        for (int off = 4; off > 0; off >>= 1)
            s += __shfl_xor_sync(0xffu, s, off);
        if (tid == 0) g_part[blockIdx.x] = s;
    }
}
__global__ void k_final2(float* __restrict__ out) {
    const int tid = threadIdx.x;  // 32
    float v = g_part[tid];
    #pragma unroll
    for (int off = 16; off > 0; off >>= 1)
        v += __shfl_xor_sync(0xffffffffu, v, off);
    if (tid == 0) out[0] = v / (float)TWO_N;
}

extern "C" void kernel_launch(void* const* d_in, const int* in_sizes, int n_in,
                              void* d_out, int out_size) {
    const float* z1 = (const float*)d_in[0];
    const float* z2 = (const float*)d_in[1];
    float* out = (float*)d_out;

    static int attr_set = 0;
    if (!attr_set) {
        cudaFuncSetAttribute(k_sim, cudaFuncAttributeMaxDynamicSharedMemorySize,
                             SMEM_BYTES);
        attr_set = 1;
    }

    k_normalize<<<TWO_N / 8, 256>>>(z1, z2);   // 8 warps/block, warp per row
    k_sim<<<NUPPER, 256, SMEM_BYTES>>>();
    k_final1<<<32, 256>>>();
    k_final2<<<1, 32>>>(out);
}